// round 1
// baseline (speedup 1.0000x reference)
#include <cuda_runtime.h>
#include <float.h>

// Problem constants (fixed by reference)
#define Bn   2
#define Cn   32          // channels per border group (C4 = 128 = 4*32)
#define Hn   128
#define Wn   128
#define Kn   (Hn * Wn)   // 16384 boxes
#define POOLSZ 10
#define Pn   (POOLSZ + 1)

// One warp handles one (b, border, k); lane = channel (0..31).
// grid: Bn*4*Kn warps = 131072 warps -> 16384 blocks x 256 threads.
__global__ __launch_bounds__(256, 8)
void border_align_kernel(const float* __restrict__ feature,
                         const float* __restrict__ boxes,
                         float* __restrict__ out)
{
    const int gtid = blockIdx.x * blockDim.x + threadIdx.x;
    const int warp = gtid >> 5;
    const int lane = threadIdx.x & 31;

    const int k      = warp & (Kn - 1);
    const int bb     = warp >> 14;       // log2(Kn) = 14
    const int border = bb & 3;
    const int b      = bb >> 2;

    // Box load: warp-uniform address -> single-sector broadcast
    const float4 box = __ldg(((const float4*)boxes) + (size_t)b * Kn + k);
    const float bx1 = box.x, by1 = box.y, bx2 = box.z, by2 = box.w;

    // Feature plane for this (b, border, channel=lane)
    const float* __restrict__ f =
        feature + ((size_t)(b * 4 + border) * Cn + lane) * (Hn * Wn);

    // Border parametrization:
    // 0: top    (y = y1, x sweeps x1..x2)
    // 1: left   (x = x1, y sweeps y1..y2)
    // 2: bottom (y = y2, x sweeps x1..x2)
    // 3: right  (x = x2, y sweeps y1..y2)
    float ox, oy, wx, wy;
    if (border == 0)      { ox = bx1; oy = by1; wx = bx2 - bx1; wy = 0.f; }
    else if (border == 1) { ox = bx1; oy = by1; wx = 0.f;       wy = by2 - by1; }
    else if (border == 2) { ox = bx1; oy = by2; wx = bx2 - bx1; wy = 0.f; }
    else                  { ox = bx2; oy = by1; wx = 0.f;       wy = by2 - by1; }

    float maxv = -FLT_MAX;

#pragma unroll
    for (int p = 0; p < Pn; p++) {
        // t = p / pool_size, then x = x1 + t*(x2-x1) with mul-then-add rounding
        // (matches reference; no FMA contraction on the coordinate path)
        const float t = __fdividef((float)p, (float)POOLSZ);
        const float x = __fadd_rn(ox, __fmul_rn(t, wx));
        const float y = __fadd_rn(oy, __fmul_rn(t, wy));

        const bool valid = (x > -1.0f) & (x < (float)Wn) &
                           (y > -1.0f) & (y < (float)Hn);

        const float xc = fminf(fmaxf(x, 0.0f), (float)(Wn - 1));
        const float yc = fminf(fmaxf(y, 0.0f), (float)(Hn - 1));

        const int x0  = (int)floorf(xc);
        const int y0  = (int)floorf(yc);
        const int x1i = min(x0 + 1, Wn - 1);
        const int y1i = min(y0 + 1, Hn - 1);

        const float lx = xc - (float)x0;
        const float ly = yc - (float)y0;

        const float* r0 = f + y0  * Wn;
        const float* r1 = f + y1i * Wn;

        const float v00 = __ldg(r0 + x0);
        const float v01 = __ldg(r0 + x1i);
        const float v10 = __ldg(r1 + x0);
        const float v11 = __ldg(r1 + x1i);

        const float vt = v00 + lx * (v01 - v00);
        const float vb = v10 + lx * (v11 - v10);
        float val = vt + ly * (vb - vt);
        val = valid ? val : 0.0f;

        maxv = fmaxf(maxv, val);
    }

    // out[b][c][k][border], c = lane
    out[(((size_t)b * Cn + lane) * Kn + k) * 4 + border] = maxv;
}

extern "C" void kernel_launch(void* const* d_in, const int* in_sizes, int n_in,
                              void* d_out, int out_size)
{
    const float* feature = (const float*)d_in[0];
    const float* boxes   = (const float*)d_in[1];
    float* out           = (float*)d_out;

    const int total_warps   = Bn * 4 * Kn;                 // 131072
    const int threads       = 256;
    const int warps_per_blk = threads / 32;
    const int blocks        = total_warps / warps_per_blk; // 16384

    border_align_kernel<<<blocks, threads>>>(feature, boxes, out);
}

// round 2
// speedup vs baseline: 4.7349x; 4.7349x over previous
#include <cuda_runtime.h>
#include <float.h>

// Problem constants (fixed by reference)
#define Bn   2
#define Cn   32          // channels per border group (C4 = 128 = 4*32)
#define Hn   128
#define Wn   128
#define Kn   (Hn * Wn)   // 16384 boxes
#define POOLSZ 10
#define Pn   (POOLSZ + 1)

// Scratch (allocation-free rule: __device__ globals)
__device__ float g_featT[Bn * 4 * Hn * Wn * Cn];  // [b][g][y][x][c]  16 MB
__device__ float g_outT [Bn * 4 * Kn * Cn];       // [b][border][k][c] 16 MB

// ---------------------------------------------------------------------------
// Kernel 1: feature [b][g][c][y][x] -> g_featT [b][g][y][x][c]
// Block (32,32): tile over (c, x) for fixed (b,g,y). 4 x-tiles per row.
// ---------------------------------------------------------------------------
__global__ __launch_bounds__(1024)
void feat_transpose_kernel(const float* __restrict__ feature)
{
    __shared__ float tile[32][33];

    const int xt  = blockIdx.x & 3;          // x-tile (0..3)
    const int y   = (blockIdx.x >> 2) & (Hn - 1);
    const int bg  = blockIdx.x >> 9;         // b*4+g  (0..7)
    const int tx  = threadIdx.x;             // 0..31
    const int ty  = threadIdx.y;             // 0..31
    const int x0  = xt * 32;

    // read: lane tx varies over x -> coalesced
    tile[ty][tx] = feature[((size_t)bg * Cn + ty) * (Hn * Wn) + y * Wn + x0 + tx];
    __syncthreads();

    // write: lane tx varies over c -> coalesced
    g_featT[(((size_t)bg * Hn + y) * Wn + (x0 + ty)) * Cn + tx] = tile[tx][ty];
}

// ---------------------------------------------------------------------------
// Kernel 2: main border-align. One warp per (b, border, k); lane = channel.
// Gathers from channels-last layout: one 128B line per corner -> 1 wavefront.
// Stores to g_outT[b][border][k][c]: coalesced 128B per warp.
// ---------------------------------------------------------------------------
__global__ __launch_bounds__(256, 8)
void border_align_kernel(const float* __restrict__ boxes)
{
    const int gtid = blockIdx.x * blockDim.x + threadIdx.x;
    const int warp = gtid >> 5;
    const int lane = threadIdx.x & 31;

    const int k      = warp & (Kn - 1);
    const int bb     = warp >> 14;       // log2(Kn) = 14
    const int border = bb & 3;
    const int b      = bb >> 2;

    // Box load: warp-uniform address -> single-sector broadcast
    const float4 box = __ldg(((const float4*)boxes) + (size_t)b * Kn + k);
    const float bx1 = box.x, by1 = box.y, bx2 = box.z, by2 = box.w;

    // Border parametrization:
    // 0: top (y=y1, x sweeps), 1: left (x=x1, y sweeps),
    // 2: bottom (y=y2, x sweeps), 3: right (x=x2, y sweeps)
    float ox, oy, wx, wy;
    if (border == 0)      { ox = bx1; oy = by1; wx = bx2 - bx1; wy = 0.f; }
    else if (border == 1) { ox = bx1; oy = by1; wx = 0.f;       wy = by2 - by1; }
    else if (border == 2) { ox = bx1; oy = by2; wx = bx2 - bx1; wy = 0.f; }
    else                  { ox = bx2; oy = by1; wx = 0.f;       wy = by2 - by1; }

    // Base of this (b, border) plane in channels-last scratch
    const float* __restrict__ f = g_featT + (size_t)(b * 4 + border) * (Hn * Wn * Cn);

    float maxv = -FLT_MAX;

#pragma unroll
    for (int p = 0; p < Pn; p++) {
        // Coordinate path: mul-then-add rounding to match reference
        const float t = __fdividef((float)p, (float)POOLSZ);
        const float x = __fadd_rn(ox, __fmul_rn(t, wx));
        const float y = __fadd_rn(oy, __fmul_rn(t, wy));

        const bool valid = (x > -1.0f) & (x < (float)Wn) &
                           (y > -1.0f) & (y < (float)Hn);

        const float xc = fminf(fmaxf(x, 0.0f), (float)(Wn - 1));
        const float yc = fminf(fmaxf(y, 0.0f), (float)(Hn - 1));

        const int x0  = (int)floorf(xc);
        const int y0  = (int)floorf(yc);
        const int x1i = min(x0 + 1, Wn - 1);
        const int y1i = min(y0 + 1, Hn - 1);

        const float lx = xc - (float)x0;
        const float ly = yc - (float)y0;

        // channels-last: (y*W + x)*C + lane -> 32 lanes = one 128B line
        const float v00 = __ldg(f + (y0  * Wn + x0 ) * Cn + lane);
        const float v01 = __ldg(f + (y0  * Wn + x1i) * Cn + lane);
        const float v10 = __ldg(f + (y1i * Wn + x0 ) * Cn + lane);
        const float v11 = __ldg(f + (y1i * Wn + x1i) * Cn + lane);

        const float vt = v00 + lx * (v01 - v00);
        const float vb = v10 + lx * (v11 - v10);
        float val = vt + ly * (vb - vt);
        val = valid ? val : 0.0f;

        maxv = fmaxf(maxv, val);
    }

    // Coalesced store: lane varies over c
    g_outT[((size_t)(b * 4 + border) * Kn + k) * Cn + lane] = maxv;
}

// ---------------------------------------------------------------------------
// Kernel 3: g_outT[b][border][k][c] -> out[b][c][k][4] (as float4 per (b,c,k))
// Block (32,32) handles (b, k-tile of 32): smem-staged transpose.
// ---------------------------------------------------------------------------
__global__ __launch_bounds__(1024)
void out_transpose_kernel(float* __restrict__ out)
{
    __shared__ float tile[4][32][33];   // [border][k'][c]

    const int kt = blockIdx.x & ((Kn / 32) - 1);  // k-tile (0..511)
    const int b  = blockIdx.x >> 9;
    const int tx = threadIdx.x;                   // 0..31
    const int ty = threadIdx.y;                   // 0..31
    const int k0 = kt * 32;

    // Load: lane tx varies over c -> coalesced; ty over k'
#pragma unroll
    for (int border = 0; border < 4; border++) {
        tile[border][ty][tx] =
            g_outT[((size_t)(b * 4 + border) * Kn + (k0 + ty)) * Cn + tx];
    }
    __syncthreads();

    // Write: thread (tx = k', ty = c) emits float4 of 4 borders.
    // Lanes tx vary over k -> consecutive float4 -> 512B coalesced store.
    float4 v;
    v.x = tile[0][tx][ty];
    v.y = tile[1][tx][ty];
    v.z = tile[2][tx][ty];
    v.w = tile[3][tx][ty];
    ((float4*)out)[((size_t)b * Cn + ty) * Kn + (k0 + tx)] = v;
}

// ---------------------------------------------------------------------------
extern "C" void kernel_launch(void* const* d_in, const int* in_sizes, int n_in,
                              void* d_out, int out_size)
{
    const float* feature = (const float*)d_in[0];
    const float* boxes   = (const float*)d_in[1];
    float* out           = (float*)d_out;

    // 1) feature -> channels-last scratch
    {
        dim3 blk(32, 32);
        int grid = Bn * 4 * Hn * (Wn / 32);   // 4096
        feat_transpose_kernel<<<grid, blk>>>(feature);
    }

    // 2) main border-align
    {
        const int total_warps   = Bn * 4 * Kn;                 // 131072
        const int threads       = 256;
        const int blocks        = total_warps / (threads / 32); // 16384
        border_align_kernel<<<blocks, threads>>>(boxes);
    }

    // 3) scratch -> final output layout
    {
        dim3 blk(32, 32);
        int grid = Bn * (Kn / 32);            // 1024
        out_transpose_kernel<<<grid, blk>>>(out);
    }
}

// round 3
// speedup vs baseline: 12.4026x; 2.6194x over previous
#include <cuda_runtime.h>
#include <float.h>

// Problem constants (fixed by reference)
#define Bn   2
#define Cn   32          // channels per border group (C4 = 128 = 4*32)
#define Hn   128
#define Wn   128
#define Kn   (Hn * Wn)   // 16384 boxes
#define POOLSZ 10
#define Pn   (POOLSZ + 1)

// Scratch (allocation-free rule: __device__ global)
__device__ float g_featT[Bn * 4 * Hn * Wn * Cn];  // [b][g][y][x][c]  16 MB

// ---------------------------------------------------------------------------
// Kernel 1: feature [b][g][c][y][x] -> g_featT [b][g][y][x][c]
// Block (8,32) = 256 threads; each thread moves 4 elements (float4).
// Tile: 32 channels x 32 x-positions for one (bg, y).
// ---------------------------------------------------------------------------
__global__ __launch_bounds__(256)
void feat_transpose_kernel(const float* __restrict__ feature)
{
    __shared__ float tile[32][37];   // [c][x'] pad=37: conflict-free both phases

    const int xt  = blockIdx.x & 3;            // x-tile (0..3)
    const int y   = (blockIdx.x >> 2) & (Hn - 1);
    const int bg  = blockIdx.x >> 9;           // b*4+g (0..7)
    const int tx  = threadIdx.x;               // 0..7
    const int ty  = threadIdx.y;               // 0..31
    const int x0  = xt * 32;

    // Load: thread (tx,ty) reads float4 over x at channel c=ty
    const float4 v = __ldg((const float4*)(feature
                     + ((size_t)bg * Cn + ty) * (Hn * Wn) + y * Wn + x0) + tx);
    tile[ty][4 * tx + 0] = v.x;
    tile[ty][4 * tx + 1] = v.y;
    tile[ty][4 * tx + 2] = v.z;
    tile[ty][4 * tx + 3] = v.w;
    __syncthreads();

    // Write: thread (tx,ty) writes float4 over c at x = x0+ty
    float4 w;
    w.x = tile[4 * tx + 0][ty];
    w.y = tile[4 * tx + 1][ty];
    w.z = tile[4 * tx + 2][ty];
    w.w = tile[4 * tx + 3][ty];
    ((float4*)(g_featT + (((size_t)bg * Hn + y) * Wn + (x0 + ty)) * Cn))[tx] = w;
}

// ---------------------------------------------------------------------------
// Kernel 2: main border-align, fused output layout.
// Warp serves 4 boxes: lane l -> box group g = l>>3, channel quad cq = l&7
// (channels 4*cq..4*cq+3 via float4). Block = 8 warps = 8 k x 4 borders, one b.
// Results staged in smem, written directly as out[b][c][k][0..3] float4.
// ---------------------------------------------------------------------------
__global__ __launch_bounds__(256)
void border_align_kernel(const float* __restrict__ boxes,
                         float* __restrict__ out)
{
    __shared__ float sm[8][4][36];   // [k'][border][c], pad 36 keeps 16B align

    const int b     = blockIdx.x >> 11;            // 2048 blocks per batch
    const int kbase = (blockIdx.x & 2047) * 8;

    const int w      = threadIdx.x >> 5;           // warp 0..7
    const int lane   = threadIdx.x & 31;
    const int border = w & 3;
    const int q      = w >> 2;                     // k-quad 0..1
    const int g      = lane >> 3;                  // box within quad 0..3
    const int cq     = lane & 7;                   // channel quad 0..7

    const int kp = 4 * q + g;                      // k' in [0,8)
    const int k  = kbase + kp;

    // Box load: 8 lanes per group share one float4 (broadcast within group)
    const float4 box = __ldg(((const float4*)boxes) + (size_t)b * Kn + k);
    const float bx1 = box.x, by1 = box.y, bx2 = box.z, by2 = box.w;

    // Border parametrization (border is warp-uniform):
    float ox, oy, wx, wy;
    if (border == 0)      { ox = bx1; oy = by1; wx = bx2 - bx1; wy = 0.f; }
    else if (border == 1) { ox = bx1; oy = by1; wx = 0.f;       wy = by2 - by1; }
    else if (border == 2) { ox = bx1; oy = by2; wx = bx2 - bx1; wy = 0.f; }
    else                  { ox = bx2; oy = by1; wx = 0.f;       wy = by2 - by1; }

    // Channels-last plane, viewed as float4 (8 quads per pixel)
    const float4* __restrict__ f4 = (const float4*)g_featT
        + (size_t)(b * 4 + border) * (Hn * Wn * (Cn / 4));

    float4 maxv = make_float4(-FLT_MAX, -FLT_MAX, -FLT_MAX, -FLT_MAX);

#pragma unroll
    for (int p = 0; p < Pn; p++) {
        // Coordinate path: mul-then-add rounding matches reference
        const float t = __fdividef((float)p, (float)POOLSZ);
        const float x = __fadd_rn(ox, __fmul_rn(t, wx));
        const float y = __fadd_rn(oy, __fmul_rn(t, wy));

        const bool valid = (x > -1.0f) & (x < (float)Wn) &
                           (y > -1.0f) & (y < (float)Hn);

        const float xc = fminf(fmaxf(x, 0.0f), (float)(Wn - 1));
        const float yc = fminf(fmaxf(y, 0.0f), (float)(Hn - 1));

        const int x0i = (int)floorf(xc);
        const int y0i = (int)floorf(yc);
        const int x1i = min(x0i + 1, Wn - 1);
        const int y1i = min(y0i + 1, Hn - 1);

        const float lx = xc - (float)x0i;
        const float ly = yc - (float)y0i;

        const int r0 = y0i * Wn, r1 = y1i * Wn;
        const float4 v00 = __ldg(f4 + (r0 + x0i) * (Cn / 4) + cq);
        const float4 v01 = __ldg(f4 + (r0 + x1i) * (Cn / 4) + cq);
        const float4 v10 = __ldg(f4 + (r1 + x0i) * (Cn / 4) + cq);
        const float4 v11 = __ldg(f4 + (r1 + x1i) * (Cn / 4) + cq);

        float4 val;
        {
            const float vt0 = v00.x + lx * (v01.x - v00.x);
            const float vb0 = v10.x + lx * (v11.x - v10.x);
            val.x = vt0 + ly * (vb0 - vt0);
            const float vt1 = v00.y + lx * (v01.y - v00.y);
            const float vb1 = v10.y + lx * (v11.y - v10.y);
            val.y = vt1 + ly * (vb1 - vt1);
            const float vt2 = v00.z + lx * (v01.z - v00.z);
            const float vb2 = v10.z + lx * (v11.z - v10.z);
            val.z = vt2 + ly * (vb2 - vt2);
            const float vt3 = v00.w + lx * (v01.w - v00.w);
            const float vb3 = v10.w + lx * (v11.w - v10.w);
            val.w = vt3 + ly * (vb3 - vt3);
        }
        if (!valid) val = make_float4(0.f, 0.f, 0.f, 0.f);

        maxv.x = fmaxf(maxv.x, val.x);
        maxv.y = fmaxf(maxv.y, val.y);
        maxv.z = fmaxf(maxv.z, val.z);
        maxv.w = fmaxf(maxv.w, val.w);
    }

    // Stage: sm[k'][border][4cq..4cq+3]  (16B-aligned, conflict-free phases)
    *(float4*)&sm[kp][border][4 * cq] = maxv;
    __syncthreads();

    // Write out[b][c][k][0..3] as float4; t = c*8 + k' -> 128B segments per c
    const int t  = threadIdx.x;
    const int c  = t >> 3;
    const int ko = t & 7;
    float4 o;
    o.x = sm[ko][0][c];
    o.y = sm[ko][1][c];
    o.z = sm[ko][2][c];
    o.w = sm[ko][3][c];
    ((float4*)out)[((size_t)b * Cn + c) * Kn + kbase + ko] = o;
}

// ---------------------------------------------------------------------------
extern "C" void kernel_launch(void* const* d_in, const int* in_sizes, int n_in,
                              void* d_out, int out_size)
{
    const float* feature = (const float*)d_in[0];
    const float* boxes   = (const float*)d_in[1];
    float* out           = (float*)d_out;

    // 1) feature -> channels-last scratch
    {
        dim3 blk(8, 32);
        int grid = Bn * 4 * Hn * (Wn / 32);   // 4096
        feat_transpose_kernel<<<grid, blk>>>(feature);
    }

    // 2) fused border-align + output layout
    {
        int grid = Bn * (Kn / 8);             // 4096
        border_align_kernel<<<grid, 256>>>(boxes, out);
    }
}

// round 4
// speedup vs baseline: 13.3906x; 1.0797x over previous
#include <cuda_runtime.h>
#include <float.h>

// Problem constants (fixed by reference)
#define Bn   2
#define Cn   32          // channels per border group (C4 = 128 = 4*32)
#define Hn   128
#define Wn   128
#define Kn   (Hn * Wn)   // 16384 boxes
#define POOLSZ 10
#define Pn   (POOLSZ + 1)

// Scratch (allocation-free rule: __device__ global)
__device__ float g_featT[Bn * 4 * Hn * Wn * Cn];  // [b][g][y][x][c]  16 MB

// ---------------------------------------------------------------------------
// Kernel 1: feature [b][g][c][y][x] -> g_featT [b][g][y][x][c]
// Block (8,32) = 256 threads; each thread moves 4 elements (float4).
// ---------------------------------------------------------------------------
__global__ __launch_bounds__(256)
void feat_transpose_kernel(const float* __restrict__ feature)
{
    __shared__ float tile[32][37];

    const int xt  = blockIdx.x & 3;
    const int y   = (blockIdx.x >> 2) & (Hn - 1);
    const int bg  = blockIdx.x >> 9;
    const int tx  = threadIdx.x;               // 0..7
    const int ty  = threadIdx.y;               // 0..31
    const int x0  = xt * 32;

    const float4 v = __ldg((const float4*)(feature
                     + ((size_t)bg * Cn + ty) * (Hn * Wn) + y * Wn + x0) + tx);
    tile[ty][4 * tx + 0] = v.x;
    tile[ty][4 * tx + 1] = v.y;
    tile[ty][4 * tx + 2] = v.z;
    tile[ty][4 * tx + 3] = v.w;
    __syncthreads();

    float4 w;
    w.x = tile[4 * tx + 0][ty];
    w.y = tile[4 * tx + 1][ty];
    w.z = tile[4 * tx + 2][ty];
    w.w = tile[4 * tx + 3][ty];
    ((float4*)(g_featT + (((size_t)bg * Hn + y) * Wn + (x0 + ty)) * Cn))[tx] = w;
}

// ---------------------------------------------------------------------------
// Border-specialized inner loop. u = fixed axis, s = sweep axis.
// USTRIDE/SSTRIDE are in float4 elements within a [H][W][C/4] plane.
// Weight mapping is symmetric, so (u,s)=(y,x) and (u,s)=(x,y) both reduce to
// the reference's bilinear weights.
// ---------------------------------------------------------------------------
template<int USTRIDE, int SSTRIDE>
__device__ __forceinline__ float4 border_sweep(const float4* __restrict__ f4q,
                                               float u, float s0, float sspan)
{
    // Fixed axis: hoisted out of the sample loop
    const bool  valid_u = (u > -1.0f) & (u < 128.0f);
    const float uc  = fminf(fmaxf(u, 0.0f), 127.0f);
    const int   u0  = (int)floorf(uc);
    const int   u1  = min(u0 + 1, 127);
    const float lu  = uc - (float)u0;
    const float wu0 = 1.0f - lu;
    const float wu1 = lu;

    const float4* __restrict__ pu0 = f4q + u0 * USTRIDE;
    const float4* __restrict__ pu1 = f4q + u1 * USTRIDE;

    // t = p/10 exactly (literals are correctly-rounded decimals == p/10)
    const float T[Pn] = {0.0f, 0.1f, 0.2f, 0.3f, 0.4f, 0.5f,
                         0.6f, 0.7f, 0.8f, 0.9f, 1.0f};

    float4 maxv = make_float4(-FLT_MAX, -FLT_MAX, -FLT_MAX, -FLT_MAX);

#pragma unroll
    for (int p = 0; p < Pn; p++) {
        const float s = __fadd_rn(s0, __fmul_rn(T[p], sspan));
        const bool valid = valid_u & (s > -1.0f) & (s < 128.0f);

        const float sc  = fminf(fmaxf(s, 0.0f), 127.0f);
        const int   si0 = (int)floorf(sc);
        const int   si1 = min(si0 + 1, 127);
        const float ls  = sc - (float)si0;

        const float w00 = wu0 * (1.0f - ls);
        const float w01 = wu0 * ls;
        const float w10 = wu1 * (1.0f - ls);
        const float w11 = wu1 * ls;

        const int o0 = si0 * SSTRIDE;
        const int o1 = si1 * SSTRIDE;

        const float4 v00 = __ldg(pu0 + o0);
        const float4 v01 = __ldg(pu0 + o1);
        const float4 v10 = __ldg(pu1 + o0);
        const float4 v11 = __ldg(pu1 + o1);

        float4 val;
        val.x = fmaf(v11.x, w11, fmaf(v10.x, w10, fmaf(v01.x, w01, v00.x * w00)));
        val.y = fmaf(v11.y, w11, fmaf(v10.y, w10, fmaf(v01.y, w01, v00.y * w00)));
        val.z = fmaf(v11.z, w11, fmaf(v10.z, w10, fmaf(v01.z, w01, v00.z * w00)));
        val.w = fmaf(v11.w, w11, fmaf(v10.w, w10, fmaf(v01.w, w01, v00.w * w00)));
        if (!valid) val = make_float4(0.f, 0.f, 0.f, 0.f);

        maxv.x = fmaxf(maxv.x, val.x);
        maxv.y = fmaxf(maxv.y, val.y);
        maxv.z = fmaxf(maxv.z, val.z);
        maxv.w = fmaxf(maxv.w, val.w);
    }
    return maxv;
}

// ---------------------------------------------------------------------------
// Kernel 2: main border-align, fused output layout.
// Warp serves 4 boxes: lane l -> box group g = l>>3, channel quad cq = l&7.
// Block = 8 warps = 8 k x 4 borders, one b. Staged in smem, written as
// out[b][c][k][0..3] float4 (coalesced 128B segments).
// ---------------------------------------------------------------------------
__global__ __launch_bounds__(256)
void border_align_kernel(const float* __restrict__ boxes,
                         float* __restrict__ out)
{
    __shared__ float sm[8][4][36];

    const int b     = blockIdx.x >> 11;
    const int kbase = (blockIdx.x & 2047) * 8;

    const int w      = threadIdx.x >> 5;
    const int lane   = threadIdx.x & 31;
    const int border = w & 3;
    const int q      = w >> 2;
    const int g      = lane >> 3;
    const int cq     = lane & 7;

    const int kp = 4 * q + g;
    const int k  = kbase + kp;

    const float4 box = __ldg(((const float4*)boxes) + (size_t)b * Kn + k);
    const float bx1 = box.x, by1 = box.y, bx2 = box.z, by2 = box.w;

    // Channels-last plane for (b, border), offset to this lane's channel quad
    const float4* __restrict__ f4q = (const float4*)g_featT
        + (size_t)(b * 4 + border) * (Hn * Wn * (Cn / 4)) + cq;

    // Border parametrization:
    // 0: top (u=y1, sweep x), 1: left (u=x1, sweep y),
    // 2: bottom (u=y2, sweep x), 3: right (u=x2, sweep y)
    float4 maxv;
    if ((border & 1) == 0) {
        // horizontal sweep: u = y (stride W*C/4 = 1024 f4), s = x (stride 8 f4)
        const float u = (border == 0) ? by1 : by2;
        maxv = border_sweep<Wn * (Cn / 4), (Cn / 4)>(f4q, u, bx1, bx2 - bx1);
    } else {
        // vertical sweep: u = x (stride 8 f4), s = y (stride 1024 f4)
        const float u = (border == 1) ? bx1 : bx2;
        maxv = border_sweep<(Cn / 4), Wn * (Cn / 4)>(f4q, u, by1, by2 - by1);
    }

    *(float4*)&sm[kp][border][4 * cq] = maxv;
    __syncthreads();

    const int t  = threadIdx.x;
    const int c  = t >> 3;
    const int ko = t & 7;
    float4 o;
    o.x = sm[ko][0][c];
    o.y = sm[ko][1][c];
    o.z = sm[ko][2][c];
    o.w = sm[ko][3][c];
    ((float4*)out)[((size_t)b * Cn + c) * Kn + kbase + ko] = o;
}

// ---------------------------------------------------------------------------
extern "C" void kernel_launch(void* const* d_in, const int* in_sizes, int n_in,
                              void* d_out, int out_size)
{
    const float* feature = (const float*)d_in[0];
    const float* boxes   = (const float*)d_in[1];
    float* out           = (float*)d_out;

    {
        dim3 blk(8, 32);
        int grid = Bn * 4 * Hn * (Wn / 32);   // 4096
        feat_transpose_kernel<<<grid, blk>>>(feature);
    }
    {
        int grid = Bn * (Kn / 8);             // 4096
        border_align_kernel<<<grid, 256>>>(boxes, out);
    }
}